// round 15
// baseline (speedup 1.0000x reference)
#include <cuda_runtime.h>

// Shapes fixed by the problem: B=2, S=8, N=2048, D=3
#define NPTS     2048
#define BS_      16
#define THREADS  128            // chamfer: 4 warps
#define QPB      256            // queries per block (2 per lane)
#define CHUNKS   (NPTS / QPB)   // 8
#define NBLK     (CHUNKS * BS_ * 2)   // 256
#define NSEGS    32
#define SEG_SLOTS 32            // 32 packed slots = 64 targets per segment
#define SORT_THREADS 256

typedef unsigned long long ull;

// Scratch: z-sorted copies (x,y,z,-0.5|p|^2) + segment z-boundaries.
__device__ float4 g_sorted[2][BS_][NPTS];   // [0]=X sorted, [1]=T sorted
__device__ float  g_segB[2][BS_][33];
__device__ float  g_part[NBLK];
__device__ float  g_cent[NBLK][3];
__device__ int    g_count;                  // zero-init; self-resets each run

__device__ __forceinline__ float smooth_l1(float d) {
    float a = fabsf(d);
    return (a < 1.0f) ? 0.5f * a * a : a - 0.5f;
}

__device__ __forceinline__ float fmax3(float a, float b, float c) {
    float d;
    asm("max.f32 %0, %1, %2, %3;" : "=f"(d) : "f"(a), "f"(b), "f"(c));
    return d;
}

// Packed 2-point score: s = px*x + py*y + pz*z + w  (w = -0.5*|t|^2).
__device__ __forceinline__ void score2(
    ull px2, ull py2, ull pz2,
    ull x2, ull y2, ull z2, ull w2,
    float& s0, float& s1)
{
    asm("{\n\t"
        ".reg .b64 t;\n\t"
        "fma.rn.f32x2 t, %4, %7, %8;\n\t"
        "fma.rn.f32x2 t, %3, %6, t;\n\t"
        "fma.rn.f32x2 t, %2, %5, t;\n\t"
        "mov.b64 {%0, %1}, t;\n\t"
        "}"
        : "=f"(s0), "=f"(s1)
        : "l"(px2), "l"(py2), "l"(pz2), "l"(x2), "l"(y2), "l"(z2), "l"(w2));
}

__device__ __forceinline__ ull pack2(float v) {
    float2 t = make_float2(v, v);
    return *reinterpret_cast<ull*>(&t);
}

// 11-bit target index packed into low mantissa bits.
__device__ __forceinline__ float key11(float s, int j) {
    return __int_as_float((__float_as_int(s) & 0xFFFFF800) | j);
}

// ───────────────────────── sort kernel ─────────────────────────
// One block per (bs, tensor): deterministic bitonic sort of (z, idx) keys,
// gather sorted coords (+precomputed -0.5|p|^2), write segment boundaries.
__global__ __launch_bounds__(SORT_THREADS) void sort_kernel(
    const float* __restrict__ X, const float* __restrict__ T)
{
    __shared__ ull keys[NPTS];      // 16 KB
    const int bs = blockIdx.x, tensor = blockIdx.y;
    const float* base = (tensor ? T : X) + (size_t)bs * NPTS * 3;
    const int tid = threadIdx.x;

    for (int i = tid; i < NPTS; i += SORT_THREADS) {
        unsigned u = __float_as_uint(base[3 * i + 2]);
        u = (u & 0x80000000u) ? ~u : (u | 0x80000000u);   // order-preserving map
        keys[i] = ((ull)u << 32) | (unsigned)i;
    }
    __syncthreads();

    for (int k = 2; k <= NPTS; k <<= 1) {
        for (int j = k >> 1; j > 0; j >>= 1) {
            for (int t = tid; t < NPTS / 2; t += SORT_THREADS) {
                int i   = 2 * t - (t & (j - 1));
                int ixj = i + j;
                ull a = keys[i], b = keys[ixj];
                bool asc = ((i & k) == 0);
                if ((a > b) == asc) { keys[i] = b; keys[ixj] = a; }
            }
            __syncthreads();
        }
    }

    for (int i = tid; i < NPTS; i += SORT_THREADS) {
        int idx = (int)(keys[i] & 0xFFFFFFFFu);
        float x = base[3 * idx], y = base[3 * idx + 1], z = base[3 * idx + 2];
        g_sorted[tensor][bs][i] = make_float4(x, y, z, -0.5f * (x * x + y * y + z * z));
    }
    if (tid <= 32) {
        float v;
        if (tid == 0)       v = -1e30f;
        else if (tid == 32) v =  1e30f;
        else {
            unsigned m = (unsigned)(keys[64 * tid] >> 32);
            m = (m & 0x80000000u) ? (m & 0x7FFFFFFFu) : ~m;   // inverse map
            v = __uint_as_float(m);
        }
        g_segB[tensor][bs][tid] = v;
    }
}

// ───────────────────────── chamfer kernel ─────────────────────────
// blockIdx.x: query chunk (0..7), blockIdx.y: bs, blockIdx.z: dir.
// Each lane owns 2 z-adjacent queries; warp scans a uniform ring of target
// segments around the home segment, pruning with gap_z^2 >= d2_best.
__global__ __launch_bounds__(THREADS, 6) void chamfer_kernel(
    const float* __restrict__ W, float* __restrict__ out)
{
    __shared__ float4 sXY[NPTS / 2];   // (x0,x1,y0,y1)  16 KB
    __shared__ float4 sZW[NPTS / 2];   // (z0,z1,w0,w1)  16 KB
    __shared__ float  sB[33];
    __shared__ float  sRed[4][4];
    __shared__ bool   sLast;

    const int bs = blockIdx.y, dir = blockIdx.z;
    const float4* refS  = g_sorted[dir ^ 1][bs];
    const float4* predS = g_sorted[dir][bs];
    const int tid  = threadIdx.x;
    const int lane = tid & 31;
    const int w    = tid >> 5;

    for (int t = tid; t < NPTS / 2; t += THREADS) {
        float4 a = refS[2 * t], b = refS[2 * t + 1];
        sXY[t] = make_float4(a.x, b.x, a.y, b.y);
        sZW[t] = make_float4(a.z, b.z, a.w, b.w);
    }
    if (tid < 33) sB[tid] = g_segB[dir ^ 1][bs][tid];
    __syncthreads();

    // Two z-adjacent queries per lane.
    const int q0 = blockIdx.x * QPB + 2 * tid;
    float4 Q0 = predS[q0], Q1 = predS[q0 + 1];
    const ull Ax = pack2(Q0.x), Ay = pack2(Q0.y), Az = pack2(Q0.z);
    const ull Bx = pack2(Q1.x), By = pack2(Q1.y), Bz = pack2(Q1.z);
    const float qz0 = Q0.z, qz1 = Q1.z;
    const float p20 = -2.0f * Q0.w, p21 = -2.0f * Q1.w;

    // Home segment of my q0 (binary search over boundaries).
    int h = 0;
    #pragma unroll
    for (int st = 16; st > 0; st >>= 1)
        if (sB[h + st] <= qz0) h += st;
    const int hm = __shfl_sync(0xFFFFFFFFu, h, 16);   // warp-uniform start

    float kA = -1e30f, kB = -1e30f;
    float d2A = 3e38f, d2B = 3e38f;
    int up = hm, dn = hm - 1;

    while (true) {
        bool upNeed = false, dnNeed = false;
        float gU = 3e38f, gD = 3e38f;
        if (up < NSEGS) {
            float b  = sB[up];
            float g0 = fmaxf(b - qz0, 0.0f), g1 = fmaxf(b - qz1, 0.0f);
            upNeed = __any_sync(0xFFFFFFFFu, (g0 * g0 < d2A) || (g1 * g1 < d2B));
            gU = __shfl_sync(0xFFFFFFFFu, g0, 16);
            if (!upNeed) up = NSEGS;          // gaps grow, d2 shrinks: close forever
        }
        if (dn >= 0) {
            float b  = sB[dn + 1];
            float g0 = fmaxf(qz0 - b, 0.0f), g1 = fmaxf(qz1 - b, 0.0f);
            dnNeed = __any_sync(0xFFFFFFFFu, (g0 * g0 < d2A) || (g1 * g1 < d2B));
            gD = __shfl_sync(0xFFFFFFFFu, g0, 16);
            if (!dnNeed) dn = -1;
        }
        int s;
        if (upNeed && dnNeed) s = (gU <= gD) ? up++ : dn--;
        else if (upNeed)      s = up++;
        else if (dnNeed)      s = dn--;
        else break;

        // Scan segment s: 32 slots (64 targets), warp-uniform broadcast LDS.
        const int slot0 = s * SEG_SLOTS;
        #pragma unroll
        for (int g = 0; g < SEG_SLOTS / 4; g++) {
            const int sl = slot0 + 4 * g;
            ulonglong2 xy0 = *(const ulonglong2*)&sXY[sl + 0];
            ulonglong2 zw0 = *(const ulonglong2*)&sZW[sl + 0];
            ulonglong2 xy1 = *(const ulonglong2*)&sXY[sl + 1];
            ulonglong2 zw1 = *(const ulonglong2*)&sZW[sl + 1];
            ulonglong2 xy2 = *(const ulonglong2*)&sXY[sl + 2];
            ulonglong2 zw2 = *(const ulonglong2*)&sZW[sl + 2];
            ulonglong2 xy3 = *(const ulonglong2*)&sXY[sl + 3];
            ulonglong2 zw3 = *(const ulonglong2*)&sZW[sl + 3];
            const int j0 = 2 * sl;
            float u0, u1;
            score2(Ax, Ay, Az, xy0.x, xy0.y, zw0.x, zw0.y, u0, u1);
            kA = fmax3(kA, key11(u0, j0 + 0), key11(u1, j0 + 1));
            score2(Bx, By, Bz, xy0.x, xy0.y, zw0.x, zw0.y, u0, u1);
            kB = fmax3(kB, key11(u0, j0 + 0), key11(u1, j0 + 1));
            score2(Ax, Ay, Az, xy1.x, xy1.y, zw1.x, zw1.y, u0, u1);
            kA = fmax3(kA, key11(u0, j0 + 2), key11(u1, j0 + 3));
            score2(Bx, By, Bz, xy1.x, xy1.y, zw1.x, zw1.y, u0, u1);
            kB = fmax3(kB, key11(u0, j0 + 2), key11(u1, j0 + 3));
            score2(Ax, Ay, Az, xy2.x, xy2.y, zw2.x, zw2.y, u0, u1);
            kA = fmax3(kA, key11(u0, j0 + 4), key11(u1, j0 + 5));
            score2(Bx, By, Bz, xy2.x, xy2.y, zw2.x, zw2.y, u0, u1);
            kB = fmax3(kB, key11(u0, j0 + 4), key11(u1, j0 + 5));
            score2(Ax, Ay, Az, xy3.x, xy3.y, zw3.x, zw3.y, u0, u1);
            kA = fmax3(kA, key11(u0, j0 + 6), key11(u1, j0 + 7));
            score2(Bx, By, Bz, xy3.x, xy3.y, zw3.x, zw3.y, u0, u1);
            kB = fmax3(kB, key11(u0, j0 + 6), key11(u1, j0 + 7));
        }

        // Conservative best-dist^2 bound from quantized keys:
        // key stole 11 mantissa bits -> |key - score| <= 2^-11 |key|.
        float lbA = fmaf(-4.8828125e-4f, fabsf(kA), kA);
        float lbB = fmaf(-4.8828125e-4f, fabsf(kB), kB);
        d2A = fmaf(-2.0f, lbA, p20);
        d2B = fmaf(-2.0f, lbB, p21);
    }

    // Decode NN and accumulate smooth-L1 + centroid sums for both queries.
    float v0 = 0.0f;
    {
        int bi = __float_as_int(kA) & 2047;
        float4 xy = sXY[bi >> 1], zw = sZW[bi >> 1];
        bool odd = bi & 1;
        float tx = odd ? xy.y : xy.x, ty = odd ? xy.w : xy.z, tz = odd ? zw.y : zw.x;
        v0 += smooth_l1(Q0.x - tx) + smooth_l1(Q0.y - ty) + smooth_l1(Q0.z - tz);
    }
    {
        int bi = __float_as_int(kB) & 2047;
        float4 xy = sXY[bi >> 1], zw = sZW[bi >> 1];
        bool odd = bi & 1;
        float tx = odd ? xy.y : xy.x, ty = odd ? xy.w : xy.z, tz = odd ? zw.y : zw.x;
        v0 += smooth_l1(Q1.x - tx) + smooth_l1(Q1.y - ty) + smooth_l1(Q1.z - tz);
    }
    float v1 = Q0.x + Q1.x, v2 = Q0.y + Q1.y, v3 = Q0.z + Q1.z;

    #pragma unroll
    for (int o = 16; o > 0; o >>= 1) {
        v0 += __shfl_down_sync(0xFFFFFFFFu, v0, o);
        v1 += __shfl_down_sync(0xFFFFFFFFu, v1, o);
        v2 += __shfl_down_sync(0xFFFFFFFFu, v2, o);
        v3 += __shfl_down_sync(0xFFFFFFFFu, v3, o);
    }
    if (lane == 0) {
        sRed[0][w] = v0; sRed[1][w] = v1; sRed[2][w] = v2; sRed[3][w] = v3;
    }
    __syncthreads();
    if (tid == 0) {
        float t0 = 0, t1 = 0, t2 = 0, t3 = 0;
        #pragma unroll
        for (int k = 0; k < 4; k++) {
            t0 += sRed[0][k]; t1 += sRed[1][k];
            t2 += sRed[2][k]; t3 += sRed[3][k];
        }
        const int bid = blockIdx.x + CHUNKS * (bs + BS_ * dir);
        g_part[bid] = t0 * W[bs] * (1.0f / (2.0f * (float)NPTS * 3.0f));
        g_cent[bid][0] = t1;
        g_cent[bid][1] = t2;
        g_cent[bid][2] = t3;
        __threadfence();
        sLast = (atomicAdd(&g_count, 1) == NBLK - 1);
    }
    __syncthreads();

    // Last block finalizes both outputs.
    if (sLast) {
        float s = 0.0f;
        for (int k = tid; k < NBLK; k += THREADS) s += g_part[k];

        float c = 0.0f;
        if (tid < 48) {
            const int b = tid / 3, d = tid % 3;
            float sx = 0.0f, st = 0.0f;
            #pragma unroll
            for (int ch = 0; ch < CHUNKS; ch++) {
                sx += g_cent[ch + CHUNKS * b][d];
                st += g_cent[ch + CHUNKS * (b + BS_)][d];
            }
            c = smooth_l1((sx - st) * (1.0f / (float)NPTS));
        }

        #pragma unroll
        for (int o = 16; o > 0; o >>= 1) {
            s += __shfl_down_sync(0xFFFFFFFFu, s, o);
            c += __shfl_down_sync(0xFFFFFFFFu, c, o);
        }
        __shared__ float fRed[2][4];
        if (lane == 0) { fRed[0][w] = s; fRed[1][w] = c; }
        __syncthreads();
        if (tid == 0) {
            float ts = 0, tc = 0;
            #pragma unroll
            for (int k = 0; k < 4; k++) { ts += fRed[0][k]; tc += fRed[1][k]; }
            out[0] = ts;
            out[1] = tc * (1.0f / 6.0f);
            g_count = 0;
        }
    }
}

extern "C" void kernel_launch(void* const* d_in, const int* in_sizes, int n_in,
                              void* d_out, int out_size) {
    const float* X = (const float*)d_in[0];   // [B,S,N,3]
    const float* T = (const float*)d_in[1];   // [B,S,N,3]
    const float* W = (const float*)d_in[2];   // [B,S]
    float* out = (float*)d_out;               // [2] -> (loss, lossc)

    dim3 sgrid(BS_, 2);
    sort_kernel<<<sgrid, SORT_THREADS>>>(X, T);

    dim3 grid(CHUNKS, BS_, 2);
    chamfer_kernel<<<grid, THREADS>>>(W, out);
}

// round 16
// speedup vs baseline: 1.0921x; 1.0921x over previous
#include <cuda_runtime.h>

// Shapes fixed by the problem: B=2, S=8, N=2048, D=3
#define NPTS     2048
#define BS_      16
#define THREADS  128            // chamfer: 4 warps
#define QPW      64             // queries per warp (2 per lane)
#define QPB      (4 * QPW)      // 256 queries per block
#define CHUNKS   (NPTS / QPB)   // 8
#define NBLK     (CHUNKS * BS_ * 2)   // 256
#define NSEGS    32
#define SEG_SLOTS 32            // 32 packed slots = 64 targets per segment
#define SORT_THREADS 1024

typedef unsigned long long ull;

__device__ float4 g_sorted[2][BS_][NPTS];   // z-sorted (x,y,z,-0.5|p|^2)
__device__ float  g_segB[2][BS_][33];
__device__ float  g_part[NBLK];
__device__ float  g_cent[NBLK][3];
__device__ int    g_count;                  // zero-init; self-resets each run

__device__ __forceinline__ float smooth_l1(float d) {
    float a = fabsf(d);
    return (a < 1.0f) ? 0.5f * a * a : a - 0.5f;
}

__device__ __forceinline__ float fmax3(float a, float b, float c) {
    float d;
    asm("max.f32 %0, %1, %2, %3;" : "=f"(d) : "f"(a), "f"(b), "f"(c));
    return d;
}

// Packed 2-point score: s = px*x + py*y + pz*z + w  (w = -0.5*|t|^2).
__device__ __forceinline__ void score2(
    ull px2, ull py2, ull pz2,
    ull x2, ull y2, ull z2, ull w2,
    float& s0, float& s1)
{
    asm("{\n\t"
        ".reg .b64 t;\n\t"
        "fma.rn.f32x2 t, %4, %7, %8;\n\t"
        "fma.rn.f32x2 t, %3, %6, t;\n\t"
        "fma.rn.f32x2 t, %2, %5, t;\n\t"
        "mov.b64 {%0, %1}, t;\n\t"
        "}"
        : "=f"(s0), "=f"(s1)
        : "l"(px2), "l"(py2), "l"(pz2), "l"(x2), "l"(y2), "l"(z2), "l"(w2));
}

__device__ __forceinline__ ull pack2(float v) {
    float2 t = make_float2(v, v);
    return *reinterpret_cast<ull*>(&t);
}

__device__ __forceinline__ float key11(float s, int j) {   // 11-bit target idx
    return __int_as_float((__float_as_int(s) & 0xFFFFF800) | j);
}
__device__ __forceinline__ float key5(float s, int ws) {   // 5-bit segment idx
    return __int_as_float((__float_as_int(s) & 0xFFFFFFE0) | ws);
}

// Scan one segment (raw seg-max, no index work) for the lane's 2 queries.
#define SCAN_SEG(SEG, MA, MB)                                              \
    do {                                                                    \
        const int slot0 = (SEG) * SEG_SLOTS;                                \
        _Pragma("unroll")                                                   \
        for (int g = 0; g < SEG_SLOTS / 4; g++) {                           \
            const int sl = slot0 + 4 * g;                                   \
            ulonglong2 xy0 = *(const ulonglong2*)&sXY[sl + 0];              \
            ulonglong2 zw0 = *(const ulonglong2*)&sZW[sl + 0];              \
            ulonglong2 xy1 = *(const ulonglong2*)&sXY[sl + 1];              \
            ulonglong2 zw1 = *(const ulonglong2*)&sZW[sl + 1];              \
            ulonglong2 xy2 = *(const ulonglong2*)&sXY[sl + 2];              \
            ulonglong2 zw2 = *(const ulonglong2*)&sZW[sl + 2];              \
            ulonglong2 xy3 = *(const ulonglong2*)&sXY[sl + 3];              \
            ulonglong2 zw3 = *(const ulonglong2*)&sZW[sl + 3];              \
            float u0, u1;                                                   \
            score2(Ax, Ay, Az, xy0.x, xy0.y, zw0.x, zw0.y, u0, u1);        \
            MA = fmax3(MA, u0, u1);                                         \
            score2(Bx, By, Bz, xy0.x, xy0.y, zw0.x, zw0.y, u0, u1);        \
            MB = fmax3(MB, u0, u1);                                         \
            score2(Ax, Ay, Az, xy1.x, xy1.y, zw1.x, zw1.y, u0, u1);        \
            MA = fmax3(MA, u0, u1);                                         \
            score2(Bx, By, Bz, xy1.x, xy1.y, zw1.x, zw1.y, u0, u1);        \
            MB = fmax3(MB, u0, u1);                                         \
            score2(Ax, Ay, Az, xy2.x, xy2.y, zw2.x, zw2.y, u0, u1);        \
            MA = fmax3(MA, u0, u1);                                         \
            score2(Bx, By, Bz, xy2.x, xy2.y, zw2.x, zw2.y, u0, u1);        \
            MB = fmax3(MB, u0, u1);                                         \
            score2(Ax, Ay, Az, xy3.x, xy3.y, zw3.x, zw3.y, u0, u1);        \
            MA = fmax3(MA, u0, u1);                                         \
            score2(Bx, By, Bz, xy3.x, xy3.y, zw3.x, zw3.y, u0, u1);        \
            MB = fmax3(MB, u0, u1);                                         \
        }                                                                   \
    } while (0)

// ───────────────────────── sort kernel ─────────────────────────
__global__ __launch_bounds__(SORT_THREADS) void sort_kernel(
    const float* __restrict__ X, const float* __restrict__ T)
{
    __shared__ ull keys[NPTS];      // 16 KB
    const int bs = blockIdx.x, tensor = blockIdx.y;
    const float* base = (tensor ? T : X) + (size_t)bs * NPTS * 3;
    const int tid = threadIdx.x;

    for (int i = tid; i < NPTS; i += SORT_THREADS) {
        unsigned u = __float_as_uint(base[3 * i + 2]);
        u = (u & 0x80000000u) ? ~u : (u | 0x80000000u);   // order-preserving
        keys[i] = ((ull)u << 32) | (unsigned)i;
    }
    __syncthreads();

    for (int k = 2; k <= NPTS; k <<= 1) {
        for (int j = k >> 1; j > 0; j >>= 1) {
            // 1024 compare slots, exactly one per thread
            int i   = 2 * tid - (tid & (j - 1));
            int ixj = i + j;
            ull a = keys[i], b = keys[ixj];
            bool asc = ((i & k) == 0);
            if ((a > b) == asc) { keys[i] = b; keys[ixj] = a; }
            __syncthreads();
        }
    }

    for (int i = tid; i < NPTS; i += SORT_THREADS) {
        int idx = (int)(keys[i] & 0xFFFFFFFFu);
        float x = base[3 * idx], y = base[3 * idx + 1], z = base[3 * idx + 2];
        g_sorted[tensor][bs][i] = make_float4(x, y, z, -0.5f * (x * x + y * y + z * z));
    }
    if (tid <= 32) {
        float v;
        if (tid == 0)       v = -1e30f;
        else if (tid == 32) v =  1e30f;
        else {
            unsigned m = (unsigned)(keys[64 * tid] >> 32);
            m = (m & 0x80000000u) ? (m & 0x7FFFFFFFu) : ~m;
            v = __uint_as_float(m);
        }
        g_segB[tensor][bs][tid] = v;
    }
}

// ───────────────────────── chamfer kernel ─────────────────────────
__global__ __launch_bounds__(THREADS, 6) void chamfer_kernel(
    const float* __restrict__ W, float* __restrict__ out)
{
    __shared__ float4 sXY[NPTS / 2];   // 16 KB
    __shared__ float4 sZW[NPTS / 2];   // 16 KB
    __shared__ float  sB[33];
    __shared__ float  sKey[QPB];       // per-query winning segment keys
    __shared__ float  sRed[4][4];
    __shared__ bool   sLast;

    const int bs = blockIdx.y, dir = blockIdx.z;
    const float4* refS  = g_sorted[dir ^ 1][bs];
    const float4* predS = g_sorted[dir][bs];
    const int tid  = threadIdx.x;
    const int lane = tid & 31;
    const int w    = tid >> 5;

    for (int t = tid; t < NPTS / 2; t += THREADS) {
        float4 a = refS[2 * t], b = refS[2 * t + 1];
        sXY[t] = make_float4(a.x, b.x, a.y, b.y);
        sZW[t] = make_float4(a.z, b.z, a.w, b.w);
    }
    if (tid < 33) sB[tid] = g_segB[dir ^ 1][bs][tid];
    __syncthreads();

    // Warp w owns 64 z-adjacent queries; lane holds 2.
    const int q0 = blockIdx.x * QPB + w * QPW + 2 * lane;
    float4 Q0 = predS[q0], Q1 = predS[q0 + 1];
    const ull Ax = pack2(Q0.x), Ay = pack2(Q0.y), Az = pack2(Q0.z);
    const ull Bx = pack2(Q1.x), By = pack2(Q1.y), Bz = pack2(Q1.z);
    const float p20 = -2.0f * Q0.w, p21 = -2.0f * Q1.w;

    // Warp-uniform home segment (mid-lane's q0).
    int h = 0;
    #pragma unroll
    for (int st = 16; st > 0; st >>= 1)
        if (sB[h + st] <= Q0.z) h += st;
    const int hm = __shfl_sync(0xFFFFFFFFu, h, 16);

    // Phase A: scan home segment -> exact d2 upper bound per query.
    float mA = -1e30f, mB = -1e30f;
    SCAN_SEG(hm, mA, mB);
    float gA = key5(mA, hm), gB = key5(mB, hm);

    float dA = sqrtf(fmaxf(fmaf(-2.0f, mA, p20), 0.0f)) * 1.0002f + 1e-6f;
    float dB = sqrtf(fmaxf(fmaf(-2.0f, mB, p21), 0.0f)) * 1.0002f + 1e-6f;
    float loZ = fminf(Q0.z - dA, Q1.z - dB);
    float hiZ = fmaxf(Q0.z + dA, Q1.z + dB);

    // Segment range covering [loZ, hiZ] (per lane, then warp-reduced).
    int lo = 0, hi = 0;
    #pragma unroll
    for (int st = 16; st > 0; st >>= 1) {
        if (sB[lo + st] <= loZ) lo += st;
        if (sB[hi + st] <  hiZ) hi += st;
    }
    lo = __reduce_min_sync(0xFFFFFFFFu, lo);
    hi = __reduce_max_sync(0xFFFFFFFFu, hi);

    // Phase B: straight-line scan of [lo, hi], skipping home.
    for (int s = lo; s <= hi; s++) {
        if (s == hm) continue;
        float nA = -1e30f, nB = -1e30f;
        SCAN_SEG(s, nA, nB);
        gA = fmaxf(gA, key5(nA, s));
        gB = fmaxf(gB, key5(nB, s));
    }

    sKey[w * QPW + 2 * lane + 0] = gA;
    sKey[w * QPW + 2 * lane + 1] = gB;
    __syncthreads();

    // Pass 2: 2 queries/thread, rescan winning segment with indexed keys.
    float v0 = 0.0f, v1 = 0.0f, v2 = 0.0f, v3 = 0.0f;
    #pragma unroll
    for (int rep = 0; rep < 2; rep++) {
        const int qi = tid + rep * THREADS;
        float4 Q = predS[blockIdx.x * QPB + qi];
        const ull qx2 = pack2(Q.x), qy2 = pack2(Q.y), qz2 = pack2(Q.z);
        const int wsWin    = __float_as_int(sKey[qi]) & 31;
        const int slotBase = wsWin * SEG_SLOTS;

        float kk = -1e30f;
        #pragma unroll 4
        for (int ii = 0; ii < SEG_SLOTS; ii++) {
            const int s = slotBase + ((ii + lane) & (SEG_SLOTS - 1));
            ulonglong2 xy = *(const ulonglong2*)&sXY[s];
            ulonglong2 zw = *(const ulonglong2*)&sZW[s];
            float u0, u1;
            score2(qx2, qy2, qz2, xy.x, xy.y, zw.x, zw.y, u0, u1);
            kk = fmax3(kk, key11(u0, 2 * s), key11(u1, 2 * s + 1));
        }
        const int bi = __float_as_int(kk) & 2047;
        float4 xy = sXY[bi >> 1], zw = sZW[bi >> 1];
        const bool odd = bi & 1;
        float tx = odd ? xy.y : xy.x;
        float ty = odd ? xy.w : xy.z;
        float tz = odd ? zw.y : zw.x;
        v0 += smooth_l1(Q.x - tx) + smooth_l1(Q.y - ty) + smooth_l1(Q.z - tz);
        v1 += Q.x; v2 += Q.y; v3 += Q.z;
    }

    #pragma unroll
    for (int o = 16; o > 0; o >>= 1) {
        v0 += __shfl_down_sync(0xFFFFFFFFu, v0, o);
        v1 += __shfl_down_sync(0xFFFFFFFFu, v1, o);
        v2 += __shfl_down_sync(0xFFFFFFFFu, v2, o);
        v3 += __shfl_down_sync(0xFFFFFFFFu, v3, o);
    }
    if (lane == 0) {
        sRed[0][w] = v0; sRed[1][w] = v1; sRed[2][w] = v2; sRed[3][w] = v3;
    }
    __syncthreads();
    if (tid == 0) {
        float t0 = 0, t1 = 0, t2 = 0, t3 = 0;
        #pragma unroll
        for (int k = 0; k < 4; k++) {
            t0 += sRed[0][k]; t1 += sRed[1][k];
            t2 += sRed[2][k]; t3 += sRed[3][k];
        }
        const int bid = blockIdx.x + CHUNKS * (bs + BS_ * dir);
        g_part[bid] = t0 * W[bs] * (1.0f / (2.0f * (float)NPTS * 3.0f));
        g_cent[bid][0] = t1;
        g_cent[bid][1] = t2;
        g_cent[bid][2] = t3;
        __threadfence();
        sLast = (atomicAdd(&g_count, 1) == NBLK - 1);
    }
    __syncthreads();

    if (sLast) {
        float s = 0.0f;
        for (int k = tid; k < NBLK; k += THREADS) s += g_part[k];

        float c = 0.0f;
        if (tid < 48) {
            const int b = tid / 3, d = tid % 3;
            float sx = 0.0f, st = 0.0f;
            #pragma unroll
            for (int ch = 0; ch < CHUNKS; ch++) {
                sx += g_cent[ch + CHUNKS * b][d];
                st += g_cent[ch + CHUNKS * (b + BS_)][d];
            }
            c = smooth_l1((sx - st) * (1.0f / (float)NPTS));
        }

        #pragma unroll
        for (int o = 16; o > 0; o >>= 1) {
            s += __shfl_down_sync(0xFFFFFFFFu, s, o);
            c += __shfl_down_sync(0xFFFFFFFFu, c, o);
        }
        __shared__ float fRed[2][4];
        if (lane == 0) { fRed[0][w] = s; fRed[1][w] = c; }
        __syncthreads();
        if (tid == 0) {
            float ts = 0, tc = 0;
            #pragma unroll
            for (int k = 0; k < 4; k++) { ts += fRed[0][k]; tc += fRed[1][k]; }
            out[0] = ts;
            out[1] = tc * (1.0f / 6.0f);
            g_count = 0;
        }
    }
}

extern "C" void kernel_launch(void* const* d_in, const int* in_sizes, int n_in,
                              void* d_out, int out_size) {
    const float* X = (const float*)d_in[0];   // [B,S,N,3]
    const float* T = (const float*)d_in[1];   // [B,S,N,3]
    const float* W = (const float*)d_in[2];   // [B,S]
    float* out = (float*)d_out;               // [2] -> (loss, lossc)

    dim3 sgrid(BS_, 2);
    sort_kernel<<<sgrid, SORT_THREADS>>>(X, T);

    dim3 grid(CHUNKS, BS_, 2);
    chamfer_kernel<<<grid, THREADS>>>(W, out);
}